// round 1
// baseline (speedup 1.0000x reference)
#include <cuda_runtime.h>
#include <cstdint>

#define N_B   4
#define DIM   32
#define VDIM  33
#define VG    (VDIM*VDIM*VDIM)        /* 35937  */
#define NVOX  (N_B*DIM*DIM*DIM)       /* 131072 */
#define FTOT  (NVOX*12)               /* 1572864 faces */
#define NVERT (N_B*VG)                /* 143748 */

/* flat float32 output offsets (reference tuple order, flattened+concat) */
#define OFF_VC    0
#define OFF_FC    4
#define OFF_VPOS  8
#define OFF_USED  (OFF_VPOS + NVERT*3)          /* 431252   */
#define OFF_EIDX  (OFF_USED + NVERT)            /* 575000   */
#define OFF_FACES (OFF_EIDX + 12*FTOT)          /* 19449368 */
#define OFF_FMASK (OFF_FACES + 3*FTOT)          /* 24167960 */
#define OFF_EMASK (OFF_FMASK + FTOT)            /* 25740824 */

/* occupancy bitmask: 32 x-bits per word, [n][z][y] -> 16 KB, L1-resident */
__device__ uint32_t g_occ[N_B][DIM][DIM];

/* vid offset of triangle vertices, j = 2*face + tri; offsets in 33^3 grid:
   VO(dz,dy,dx) = dz*1089 + dy*33 + dx.  Derived from QUAD_OFFS + TRI_SEL. */
__constant__ int TRIV[12][3] = {
    {   0,    1,   33}, {   1,   33,   34},   /* f0: -z */
    {1089, 1090, 1122}, {1090, 1122, 1123},   /* f1: +z */
    {1089, 1090,    0}, {1090,    0,    1},   /* f2: -y */
    {  33,   34, 1122}, {  34, 1122, 1123},   /* f3: +y */
    {1089,    0, 1122}, {   0, 1122,   33},   /* f4: -x */
    {   1, 1090,   34}, {1090,   34, 1123}    /* f5: +x */
};
/* edge slot -> (src vertex sel, dst vertex sel) of the triangle
   slots: (0,1) (1,2) (0,2) then reversed (1,0) (2,1) (2,0) */
__constant__ int ESEL[6][2] = {{0,1},{1,2},{0,2},{1,0},{2,1},{2,0}};

/* ------------------------------------------------------------------ */
__global__ void k_occ(const float* __restrict__ p, float* __restrict__ out) {
    int tid = blockIdx.x * blockDim.x + threadIdx.x;      /* < NVOX */
    if (tid < 8) out[tid] = 0.0f;                          /* zero count slots */
    float v = p[tid];                                      /* linear == (n,z,y,x) */
    unsigned m = __ballot_sync(0xffffffffu, v > 0.5f);     /* lane == x */
    if ((tid & 31) == 0)
        reinterpret_cast<uint32_t*>(g_occ)[tid >> 5] = m;
}

/* 6 exposure bits (f0..f5) for voxel (n,z,y,x) */
__device__ __forceinline__ unsigned expo_bits(int n, int z, int y, int x) {
    uint32_t wc = g_occ[n][z][y];
    if (!((wc >> x) & 1u)) return 0u;
    uint32_t wzm = (z > 0)  ? g_occ[n][z-1][y] : 0u;
    uint32_t wzp = (z < 31) ? g_occ[n][z+1][y] : 0u;
    uint32_t wym = (y > 0)  ? g_occ[n][z][y-1] : 0u;
    uint32_t wyp = (y < 31) ? g_occ[n][z][y+1] : 0u;
    unsigned e = 0;
    e |= ((~(wzm >> x)) & 1u) << 0;
    e |= ((~(wzp >> x)) & 1u) << 1;
    e |= ((~(wym >> x)) & 1u) << 2;
    e |= ((~(wyp >> x)) & 1u) << 3;
    unsigned xm = (x > 0)  ? ((wc >> (x-1)) & 1u) : 0u;
    unsigned xp = (x < 31) ? ((wc >> (x+1)) & 1u) : 0u;
    e |= (xm ^ 1u) << 4;
    e |= (xp ^ 1u) << 5;
    return e;
}

/* ------------------------------------------------------------------ */
/* used(v): the 8 voxels around vertex v (OOB = empty) not all equal. */
__global__ void k_vert(float* __restrict__ out) {
    __shared__ int sc[N_B];
    if (threadIdx.x < N_B) sc[threadIdx.x] = 0;
    __syncthreads();

    int idx = blockIdx.x * blockDim.x + threadIdx.x;
    if (idx < NVERT) {
        int n  = idx / VG;
        int r  = idx - n * VG;
        int gz = r / 1089;  int r2 = r - gz * 1089;
        int gy = r2 / 33;   int gx = r2 - gy * 33;

        unsigned anyb = 0u, allb = 1u;
        #pragma unroll
        for (int dz = 0; dz < 2; dz++)
        #pragma unroll
        for (int dy = 0; dy < 2; dy++) {
            int z = gz - dz, y = gy - dy;
            uint32_t w = (z >= 0 && z < 32 && y >= 0 && y < 32) ? g_occ[n][z][y] : 0u;
            unsigned b0 = (gx < 32) ? ((w >> gx) & 1u) : 0u;
            unsigned b1 = (gx >= 1) ? ((w >> (gx - 1)) & 1u) : 0u;
            anyb |= b0 | b1;
            allb &= b0 & b1;
        }
        unsigned used = anyb & (allb ^ 1u);
        out[OFF_USED + idx] = (float)used;
        float m = used ? 1.0f : 0.0f;
        out[OFF_VPOS + 3*idx + 0] = m * ((float)gz - 0.5f);
        out[OFF_VPOS + 3*idx + 1] = m * ((float)gy - 0.5f);
        out[OFF_VPOS + 3*idx + 2] = m * ((float)gx - 0.5f);
        if (used) atomicAdd(&sc[n], 1);
    }
    __syncthreads();
    if (threadIdx.x < N_B && sc[threadIdx.x])
        atomicAdd(&out[OFF_VC + threadIdx.x], (float)sc[threadIdx.x]);
}

/* ------------------------------------------------------------------ */
/* per voxel: 12 faces (36 floats, 9xSTG.128) + 12 mask floats (3xSTG.128) */
__global__ void k_face(float* __restrict__ out) {
    int vox = blockIdx.x * blockDim.x + threadIdx.x;      /* < NVOX */
    int x = vox & 31, y = (vox >> 5) & 31, z = (vox >> 10) & 31, n = vox >> 15;
    unsigned e = expo_bits(n, z, y, x);
    int base = n * VG + z * 1089 + y * 33 + x;

    float fv[36], fm[12];
    #pragma unroll
    for (int j = 0; j < 12; j++) {
        fv[3*j + 0] = (float)(base + TRIV[j][0]);
        fv[3*j + 1] = (float)(base + TRIV[j][1]);
        fv[3*j + 2] = (float)(base + TRIV[j][2]);
        fm[j] = (float)((e >> (j >> 1)) & 1u);
    }
    float4* dF = (float4*)(out + OFF_FACES + (size_t)vox * 36);
    #pragma unroll
    for (int q = 0; q < 9; q++)
        dF[q] = make_float4(fv[4*q], fv[4*q+1], fv[4*q+2], fv[4*q+3]);
    float4* dM = (float4*)(out + OFF_FMASK + (size_t)vox * 12);
    #pragma unroll
    for (int q = 0; q < 3; q++)
        dM[q] = make_float4(fm[4*q], fm[4*q+1], fm[4*q+2], fm[4*q+3]);

    /* face count = 2 * popc(exposure); n uniform per warp (32768 %% 32 == 0) */
    int cnt = 2 * __popc(e);
    #pragma unroll
    for (int o = 16; o > 0; o >>= 1) cnt += __shfl_down_sync(0xffffffffu, cnt, o);
    if ((threadIdx.x & 31) == 0 && cnt)
        atomicAdd(&out[OFF_FC + n], (float)cnt);
}

/* ------------------------------------------------------------------ */
/* per (slot=blockIdx.y, voxel): 12 src + 12 dst + 12 mask floats      */
__global__ void k_edge(float* __restrict__ out) {
    int vox  = blockIdx.x * blockDim.x + threadIdx.x;     /* < NVOX */
    int slot = blockIdx.y;                                /* 0..5   */
    int x = vox & 31, y = (vox >> 5) & 31, z = (vox >> 10) & 31, n = vox >> 15;
    unsigned e = expo_bits(n, z, y, x);
    int base = n * VG + z * 1089 + y * 33 + x;
    int ss = ESEL[slot][0], dd = ESEL[slot][1];

    float r0[12], r1[12], mk[12];
    #pragma unroll
    for (int j = 0; j < 12; j++) {
        r0[j] = (float)(base + TRIV[j][ss]);
        r1[j] = (float)(base + TRIV[j][dd]);
        mk[j] = (float)((e >> (j >> 1)) & 1u);
    }
    size_t col = (size_t)slot * FTOT + (size_t)vox * 12;
    float4* p0 = (float4*)(out + OFF_EIDX + col);
    float4* p1 = (float4*)(out + OFF_EIDX + (size_t)6 * FTOT + col);
    float4* pm = (float4*)(out + OFF_EMASK + col);
    #pragma unroll
    for (int q = 0; q < 3; q++) {
        p0[q] = make_float4(r0[4*q], r0[4*q+1], r0[4*q+2], r0[4*q+3]);
        p1[q] = make_float4(r1[4*q], r1[4*q+1], r1[4*q+2], r1[4*q+3]);
        pm[q] = make_float4(mk[4*q], mk[4*q+1], mk[4*q+2], mk[4*q+3]);
    }
}

/* ------------------------------------------------------------------ */
extern "C" void kernel_launch(void* const* d_in, const int* in_sizes, int n_in,
                              void* d_out, int out_size) {
    const float* p = (const float*)d_in[0];
    float* out = (float*)d_out;
    (void)in_sizes; (void)n_in; (void)out_size;

    k_occ <<<NVOX / 256, 256>>>(p, out);
    k_vert<<<(NVERT + 255) / 256, 256>>>(out);
    k_face<<<NVOX / 256, 256>>>(out);
    dim3 ge(NVOX / 256, 6);
    k_edge<<<ge, 256>>>(out);
}

// round 2
// speedup vs baseline: 1.6540x; 1.6540x over previous
#include <cuda_runtime.h>
#include <cstdint>

#define N_B   4
#define DIM   32
#define VG    35937                    /* 33^3 */
#define NVOX  131072                   /* 4*32^3 */
#define FTOT  1572864                  /* NVOX*12 faces */
#define F4    (FTOT/4)                 /* 393216 float4 per segment */
#define NVERT (N_B*VG)                 /* 143748 */

/* flat float32 output offsets (reference tuple order, flattened + concat) */
#define OFF_VC    0
#define OFF_FC    4
#define OFF_VPOS  8
#define OFF_USED  (OFF_VPOS + NVERT*3)          /* 431252   */
#define OFF_EIDX  (OFF_USED + NVERT)            /* 575000   */
#define OFF_FACES (OFF_EIDX + 12*FTOT)          /* 19449368 */
#define OFF_FMASK (OFF_FACES + 3*FTOT)          /* 24167960 */
#define OFF_EMASK (OFF_FMASK + FTOT)            /* 25740824 */

/* block-range dispatch inside the fat kernel */
#define FB 4608                        /* faces:  4608*256 = 1179648 = 3*FTOT/4 f4 */
#define EB 1536                        /* edges:  1536*256 = 393216 = F4          */
#define MB 1536                        /* masks:  same thread count               */
#define VB 562                         /* verts:  562*256 >= 143748               */
#define GB (FB+EB+MB+VB)               /* 8242 blocks                             */

/* occupancy bitmask: 32 x-bits per word, [n][z][y] -> 16 KB, L2/L1-resident */
__device__ uint32_t g_occ[N_B][DIM][DIM];

/* vertex-id offsets in the 33^3 grid, j-major flat: TF[j*3+c], j=2*face+tri.
   VO(dz,dy,dx) = dz*1089 + dy*33 + dx, derived from QUAD_OFFS+TRI_SEL. */
__constant__ int c_TF[36] = {
       0,    1,   33,     1,   33,   34,    /* f0 -z */
    1089, 1090, 1122,  1090, 1122, 1123,    /* f1 +z */
    1089, 1090,    0,  1090,    0,    1,    /* f2 -y */
      33,   34, 1122,    34, 1122, 1123,    /* f3 +y */
    1089,    0, 1122,     0, 1122,   33,    /* f4 -x */
       1, 1090,   34,  1090,   34, 1123     /* f5 +x */
};

/* ------------------------------------------------------------------ */
__global__ void k_occ(const float* __restrict__ p, float* __restrict__ out) {
    int tid = blockIdx.x * blockDim.x + threadIdx.x;      /* < NVOX */
    if (tid < 8) out[tid] = 0.0f;                          /* zero count slots */
    float v = p[tid];                                      /* linear == (n,z,y,x) */
    unsigned m = __ballot_sync(0xffffffffu, v > 0.5f);     /* lane == x */
    if ((tid & 31) == 0)
        reinterpret_cast<uint32_t*>(g_occ)[tid >> 5] = m;
}

/* 6 exposure bits (f0..f5) for voxel (n,z,y,x) */
__device__ __forceinline__ unsigned expo_bits(int n, int z, int y, int x) {
    uint32_t wc = g_occ[n][z][y];
    if (!((wc >> x) & 1u)) return 0u;
    uint32_t wzm = (z > 0)  ? g_occ[n][z-1][y] : 0u;
    uint32_t wzp = (z < 31) ? g_occ[n][z+1][y] : 0u;
    uint32_t wym = (y > 0)  ? g_occ[n][z][y-1] : 0u;
    uint32_t wyp = (y < 31) ? g_occ[n][z][y+1] : 0u;
    unsigned e = 0;
    e |= ((~(wzm >> x)) & 1u) << 0;
    e |= ((~(wzp >> x)) & 1u) << 1;
    e |= ((~(wym >> x)) & 1u) << 2;
    e |= ((~(wyp >> x)) & 1u) << 3;
    unsigned xm = (x > 0)  ? ((wc >> (x-1)) & 1u) : 0u;
    unsigned xp = (x < 31) ? ((wc >> (x+1)) & 1u) : 0u;
    e |= (xm ^ 1u) << 4;
    e |= (xp ^ 1u) << 5;
    return e;
}

__device__ __forceinline__ int vox_base(int vox, int& n, int& z, int& y, int& x) {
    x = vox & 31; y = (vox >> 5) & 31; z = (vox >> 10) & 31; n = vox >> 15;
    return n * VG + z * 1089 + y * 33 + x;
}

/* ------------------------------------------------------------------ */
/* one fat kernel: faces | edge_index | masks | vertices, dispatched by block */
__global__ void __launch_bounds__(256) k_main(float* __restrict__ out) {
    __shared__ float s_tf[36];
    __shared__ int   sc[N_B];
    int tid = threadIdx.x;
    if (tid < 36) s_tf[tid] = (float)c_TF[tid];
    if (tid < N_B) sc[tid] = 0;
    __syncthreads();

    int b = blockIdx.x;

    if (b < FB) {
        /* ---- faces: thread t writes float4 #t, t = vox*9+q, floats 4q..4q+3 */
        int t   = b * 256 + tid;
        int vox = t / 9;
        int q   = t - vox * 9;
        int n, z, y, x;
        float bf = (float)vox_base(vox, n, z, y, x);
        int i0 = 4 * q;
        float4 v = make_float4(bf + s_tf[i0], bf + s_tf[i0+1],
                               bf + s_tf[i0+2], bf + s_tf[i0+3]);
        ((float4*)(out + OFF_FACES))[t] = v;
        return;
    }
    if (b < FB + EB) {
        /* ---- edge_index: thread t = vox*3+q; 3 distinct contents (sel 0/1/2),
           each replicated into 4 of the 12 segments, all stores coalesced   */
        int t   = (b - FB) * 256 + tid;
        int vox = t / 3;
        int q   = t - vox * 3;
        int n, z, y, x;
        float bf = (float)vox_base(vox, n, z, y, x);
        int j0 = 4 * q;                      /* triangles j0..j0+3 */
        float4 v0 = make_float4(bf + s_tf[3*j0+0], bf + s_tf[3*(j0+1)+0],
                                bf + s_tf[3*(j0+2)+0], bf + s_tf[3*(j0+3)+0]);
        float4 v1 = make_float4(bf + s_tf[3*j0+1], bf + s_tf[3*(j0+1)+1],
                                bf + s_tf[3*(j0+2)+1], bf + s_tf[3*(j0+3)+1]);
        float4 v2 = make_float4(bf + s_tf[3*j0+2], bf + s_tf[3*(j0+1)+2],
                                bf + s_tf[3*(j0+2)+2], bf + s_tf[3*(j0+3)+2]);
        float4* E = (float4*)(out + OFF_EIDX);
        /* row0 sels: 0,1,0,1,2,2  row1 sels: 1,2,2,0,1,0 */
        E[ 0*F4 + t] = v0;  E[ 2*F4 + t] = v0;  E[ 9*F4 + t] = v0;  E[11*F4 + t] = v0;
        E[ 1*F4 + t] = v1;  E[ 3*F4 + t] = v1;  E[ 6*F4 + t] = v1;  E[10*F4 + t] = v1;
        E[ 4*F4 + t] = v2;  E[ 5*F4 + t] = v2;  E[ 7*F4 + t] = v2;  E[ 8*F4 + t] = v2;
        return;
    }
    if (b < FB + EB + MB) {
        /* ---- masks: face_mask + 6 identical edge_mask segments */
        int t   = (b - FB - EB) * 256 + tid;
        int vox = t / 3;
        int q   = t - vox * 3;
        int n, z, y, x;
        (void)vox_base(vox, n, z, y, x);
        unsigned e = expo_bits(n, z, y, x);
        float a0 = (float)((e >> (2*q    )) & 1u);
        float a1 = (float)((e >> (2*q + 1)) & 1u);
        float4 m = make_float4(a0, a0, a1, a1);
        ((float4*)(out + OFF_FMASK))[t] = m;
        float4* EM = (float4*)(out + OFF_EMASK);
        #pragma unroll
        for (int s = 0; s < 6; s++) EM[s*F4 + t] = m;

        /* face counts: only q==0 lane of each voxel contributes 2*popc(e);
           n is warp-uniform (phase thread-count boundaries divide 98304) */
        int cnt = (q == 0) ? 2 * __popc(e) : 0;
        #pragma unroll
        for (int o = 16; o > 0; o >>= 1) cnt += __shfl_down_sync(0xffffffffu, cnt, o);
        if ((tid & 31) == 0 && cnt)
            atomicAdd(&out[OFF_FC + n], (float)cnt);
        return;
    }
    /* ---- vertices: used / vpos / vert_counts */
    {
        int idx = (b - FB - EB - MB) * 256 + tid;
        if (idx < NVERT) {
            int n  = idx / VG;
            int r  = idx - n * VG;
            int gz = r / 1089;  int r2 = r - gz * 1089;
            int gy = r2 / 33;   int gx = r2 - gy * 33;

            unsigned anyb = 0u, allb = 1u;
            #pragma unroll
            for (int dz = 0; dz < 2; dz++)
            #pragma unroll
            for (int dy = 0; dy < 2; dy++) {
                int z = gz - dz, y = gy - dy;
                uint32_t w = (z >= 0 && z < 32 && y >= 0 && y < 32) ? g_occ[n][z][y] : 0u;
                unsigned b0 = (gx < 32) ? ((w >> gx) & 1u) : 0u;
                unsigned b1 = (gx >= 1) ? ((w >> (gx - 1)) & 1u) : 0u;
                anyb |= b0 | b1;
                allb &= b0 & b1;
            }
            unsigned used = anyb & (allb ^ 1u);
            out[OFF_USED + idx] = (float)used;
            float m = used ? 1.0f : 0.0f;
            out[OFF_VPOS + 3*idx + 0] = m * ((float)gz - 0.5f);
            out[OFF_VPOS + 3*idx + 1] = m * ((float)gy - 0.5f);
            out[OFF_VPOS + 3*idx + 2] = m * ((float)gx - 0.5f);
            if (used) atomicAdd(&sc[n], 1);
        }
        __syncthreads();
        if (tid < N_B && sc[tid])
            atomicAdd(&out[OFF_VC + tid], (float)sc[tid]);
    }
}

/* ------------------------------------------------------------------ */
extern "C" void kernel_launch(void* const* d_in, const int* in_sizes, int n_in,
                              void* d_out, int out_size) {
    const float* p = (const float*)d_in[0];
    float* out = (float*)d_out;
    (void)in_sizes; (void)n_in; (void)out_size;

    k_occ <<<NVOX / 256, 256>>>(p, out);
    k_main<<<GB, 256>>>(out);
}